// round 2
// baseline (speedup 1.0000x reference)
#include <cuda_runtime.h>

// ---------------------------------------------------------------------------
// GRU encoder-decoder, persistent per-CTA recurrence.
// B=4096 rows, H=64, T=256 enc steps, TL dec steps (derived from out_size).
// One CTA = 32 batch rows; all weights in SMEM (k-major transpose); hidden
// states ping through SMEM in [k][row] layout for float4 loads.
// Thread tile: 4 rows x 2 hidden units, computing r/z/n gates locally so the
// nonlinear epilogue needs no cross-thread exchange.
// ---------------------------------------------------------------------------

#define Hh     64
#define G3     192
#define ROWS   32
#define NT     256
#define TSEQ   256
#define NINP   6

// SMEM float offsets
#define OFF_WX0   0        // [8][192]  (enc: 6 rows used; dec: 1 row used)
#define OFF_WH0   1536     // [64][192]
#define OFF_WX1   13824    // [64][192]
#define OFF_WH1   26112    // [64][192]
#define OFF_BIH0  38400    // [192]
#define OFF_BHH0  38592
#define OFF_BIH1  38784
#define OFF_BHH1  38976
#define OFF_OUTW  39168    // [64]
#define OFF_OUTB  39232    // [1]
#define OFF_HS0   39236    // [64][32]
#define OFF_HS1   41284    // [64][32]
#define OFF_XS    43332    // [8][32]  (enc: x_t staged; dec: prev cv in row 0)
#define SMEM_FLOATS 43588  // 174,352 bytes

__device__ __forceinline__ float sigf(float x) {
    return 1.0f / (1.0f + __expf(-x));
}

__device__ __forceinline__ float tanhfast(float x) {
    // tanh via exp of non-positive argument (no overflow path), ~1e-6 rel err
    float e = __expf(-2.0f * fabsf(x));
    float t = (1.0f - e) / (1.0f + e);
    return copysignf(t, x);
}

// Transpose-load W[192][K] (row-major) -> dst[k*192 + g]
__device__ __forceinline__ void load_wT(float* dst, const float* __restrict__ src,
                                        int K, int tid) {
    for (int idx = tid; idx < G3 * K; idx += NT) {
        int g = idx / K;
        int k = idx - g * K;
        dst[k * G3 + g] = src[idx];
    }
}

// One GRU cell for this thread's [2 units x 4 rows] tile.
// xsrc/hsrc are k-major [k][ROWS]; Wx/Wh are k-major [k][192] with gate order
// r(0..63), z(64..127), n(128..191).
template<int KIN>
__device__ __forceinline__ void gru_tile(
    const float* __restrict__ Wx, const float* __restrict__ Wh,
    const float* __restrict__ xsrc, const float* __restrict__ hsrc,
    const float* __restrict__ bih, const float* __restrict__ bhh,
    int j0, int r0, float hnew[2][4])
{
    float ar[2][4], az[2][4], ai[2][4], ah[2][4];
#pragma unroll
    for (int u = 0; u < 2; u++) {
        float br = bih[j0 + u] + bhh[j0 + u];
        float bz = bih[64 + j0 + u] + bhh[64 + j0 + u];
        float bi = bih[128 + j0 + u];
        float bh = bhh[128 + j0 + u];
#pragma unroll
        for (int rr = 0; rr < 4; rr++) {
            ar[u][rr] = br; az[u][rr] = bz; ai[u][rr] = bi; ah[u][rr] = bh;
        }
    }

    // input contribution
#pragma unroll 8
    for (int k = 0; k < KIN; k++) {
        float4 xv = *(const float4*)(xsrc + k * ROWS + r0);
        float xw[4] = {xv.x, xv.y, xv.z, xv.w};
        float2 wr = *(const float2*)(Wx + k * G3 + j0);
        float2 wz = *(const float2*)(Wx + k * G3 + 64 + j0);
        float2 wn = *(const float2*)(Wx + k * G3 + 128 + j0);
        float wru[2] = {wr.x, wr.y}, wzu[2] = {wz.x, wz.y}, wnu[2] = {wn.x, wn.y};
#pragma unroll
        for (int u = 0; u < 2; u++)
#pragma unroll
            for (int rr = 0; rr < 4; rr++) {
                ar[u][rr] = fmaf(wru[u], xw[rr], ar[u][rr]);
                az[u][rr] = fmaf(wzu[u], xw[rr], az[u][rr]);
                ai[u][rr] = fmaf(wnu[u], xw[rr], ai[u][rr]);
            }
    }

    // hidden contribution
#pragma unroll 8
    for (int k = 0; k < Hh; k++) {
        float4 hv = *(const float4*)(hsrc + k * ROWS + r0);
        float hw[4] = {hv.x, hv.y, hv.z, hv.w};
        float2 wr = *(const float2*)(Wh + k * G3 + j0);
        float2 wz = *(const float2*)(Wh + k * G3 + 64 + j0);
        float2 wn = *(const float2*)(Wh + k * G3 + 128 + j0);
        float wru[2] = {wr.x, wr.y}, wzu[2] = {wz.x, wz.y}, wnu[2] = {wn.x, wn.y};
#pragma unroll
        for (int u = 0; u < 2; u++)
#pragma unroll
            for (int rr = 0; rr < 4; rr++) {
                ar[u][rr] = fmaf(wru[u], hw[rr], ar[u][rr]);
                az[u][rr] = fmaf(wzu[u], hw[rr], az[u][rr]);
                ah[u][rr] = fmaf(wnu[u], hw[rr], ah[u][rr]);
            }
    }

    // epilogue: r,z sigmoid; n = tanh(in + r*hn); h' = n + z*(h - n)
#pragma unroll
    for (int u = 0; u < 2; u++)
#pragma unroll
        for (int rr = 0; rr < 4; rr++) {
            float hold = hsrc[(j0 + u) * ROWS + r0 + rr];
            float r = sigf(ar[u][rr]);
            float z = sigf(az[u][rr]);
            float n = tanhfast(fmaf(r, ah[u][rr], ai[u][rr]));
            hnew[u][rr] = fmaf(z, hold - n, n);
        }
}

__device__ __forceinline__ void write_h(float* hdst, int j0, int r0,
                                        const float hnew[2][4]) {
#pragma unroll
    for (int u = 0; u < 2; u++) {
        *(float4*)(hdst + (j0 + u) * ROWS + r0) =
            make_float4(hnew[u][0], hnew[u][1], hnew[u][2], hnew[u][3]);
    }
}

extern __shared__ float sm[];

__global__ __launch_bounds__(NT, 1)
void gru_kernel(
    const float* __restrict__ x,
    const float* __restrict__ eWih0, const float* __restrict__ eWhh0,
    const float* __restrict__ ebih0, const float* __restrict__ ebhh0,
    const float* __restrict__ eWih1, const float* __restrict__ eWhh1,
    const float* __restrict__ ebih1, const float* __restrict__ ebhh1,
    const float* __restrict__ dWih0, const float* __restrict__ dWhh0,
    const float* __restrict__ dbih0, const float* __restrict__ dbhh0,
    const float* __restrict__ dWih1, const float* __restrict__ dWhh1,
    const float* __restrict__ dbih1, const float* __restrict__ dbhh1,
    const float* __restrict__ outW, const float* __restrict__ outb,
    float* __restrict__ out, int Bn, int TL)
{
    const int tid = threadIdx.x;
    const int b0  = blockIdx.x * ROWS;

    float* Wx0  = sm + OFF_WX0;
    float* Wh0  = sm + OFF_WH0;
    float* Wx1  = sm + OFF_WX1;
    float* Wh1  = sm + OFF_WH1;
    float* bih0 = sm + OFF_BIH0;
    float* bhh0 = sm + OFF_BHH0;
    float* bih1 = sm + OFF_BIH1;
    float* bhh1 = sm + OFF_BHH1;
    float* sOW  = sm + OFF_OUTW;
    float* sOB  = sm + OFF_OUTB;
    float* hs0  = sm + OFF_HS0;
    float* hs1  = sm + OFF_HS1;
    float* xs   = sm + OFF_XS;

    // ---- stage encoder weights ----
    load_wT(Wx0, eWih0, NINP, tid);
    load_wT(Wh0, eWhh0, Hh, tid);
    load_wT(Wx1, eWih1, Hh, tid);
    load_wT(Wh1, eWhh1, Hh, tid);
    for (int i = tid; i < G3; i += NT) {
        bih0[i] = ebih0[i]; bhh0[i] = ebhh0[i];
        bih1[i] = ebih1[i]; bhh1[i] = ebhh1[i];
    }
    for (int i = tid; i < Hh * ROWS; i += NT) { hs0[i] = 0.0f; hs1[i] = 0.0f; }
    __syncthreads();

    const int rt = tid & 7;          // row tile 0..7
    const int ut = tid >> 3;         // unit tile 0..31
    const int r0 = rt * 4;
    const int j0 = ut * 2;
    float hnew[2][4];

    // ---- encoder: 256 steps, both layers fused per step ----
    for (int t = 0; t < TSEQ; t++) {
        if (tid < NINP * ROWS) {
            int i = tid >> 5;        // feature 0..5
            int r = tid & 31;        // row
            float v = 0.0f;
            if (b0 + r < Bn)
                v = x[(size_t)(b0 + r) * (TSEQ * NINP) + (size_t)t * NINP + i];
            xs[i * ROWS + r] = v;
        }
        __syncthreads();
        gru_tile<NINP>(Wx0, Wh0, xs, hs0, bih0, bhh0, j0, r0, hnew);
        __syncthreads();
        write_h(hs0, j0, r0, hnew);
        __syncthreads();
        gru_tile<Hh>(Wx1, Wh1, hs0, hs1, bih1, bhh1, j0, r0, hnew);
        __syncthreads();
        write_h(hs1, j0, r0, hnew);
        __syncthreads();
    }

    // ---- swap in decoder weights (enc weights fully consumed) ----
    load_wT(Wx0, dWih0, 1, tid);     // [192] at k=0
    load_wT(Wh0, dWhh0, Hh, tid);
    load_wT(Wx1, dWih1, Hh, tid);
    load_wT(Wh1, dWhh1, Hh, tid);
    for (int i = tid; i < G3; i += NT) {
        bih0[i] = dbih0[i]; bhh0[i] = dbhh0[i];
        bih1[i] = dbih1[i]; bhh1[i] = dbhh1[i];
    }
    if (tid < Hh) sOW[tid] = outW[tid];
    if (tid == 0) sOB[0] = outb[0];
    if (tid < ROWS) xs[tid] = 0.0f;  // prev cv = 0
    __syncthreads();

    // ---- decoder: TL autoregressive steps ----
    for (int s = 0; s < TL; s++) {
        gru_tile<1>(Wx0, Wh0, xs, hs0, bih0, bhh0, j0, r0, hnew);
        __syncthreads();
        write_h(hs0, j0, r0, hnew);
        __syncthreads();
        gru_tile<Hh>(Wx1, Wh1, hs0, hs1, bih1, bhh1, j0, r0, hnew);
        __syncthreads();
        write_h(hs1, j0, r0, hnew);
        __syncthreads();
        if (tid < ROWS) {
            float acc = sOB[0];
            #pragma unroll 8
            for (int j = 0; j < Hh; j++)
                acc = fmaf(sOW[j], hs1[j * ROWS + tid], acc);
            if (b0 + tid < Bn)
                out[(size_t)(b0 + tid) * TL + s] = acc;
            xs[tid] = acc;           // feed back as next prev
        }
        __syncthreads();
    }
}

extern "C" void kernel_launch(void* const* d_in, const int* in_sizes, int n_in,
                              void* d_out, int out_size) {
    const float* x      = (const float*)d_in[0];
    const float* eWih0  = (const float*)d_in[1];
    const float* eWhh0  = (const float*)d_in[2];
    const float* ebih0  = (const float*)d_in[3];
    const float* ebhh0  = (const float*)d_in[4];
    const float* eWih1  = (const float*)d_in[5];
    const float* eWhh1  = (const float*)d_in[6];
    const float* ebih1  = (const float*)d_in[7];
    const float* ebhh1  = (const float*)d_in[8];
    const float* dWih0  = (const float*)d_in[9];
    const float* dWhh0  = (const float*)d_in[10];
    const float* dbih0  = (const float*)d_in[11];
    const float* dbhh0  = (const float*)d_in[12];
    const float* dWih1  = (const float*)d_in[13];
    const float* dWhh1  = (const float*)d_in[14];
    const float* dbih1  = (const float*)d_in[15];
    const float* dbhh1  = (const float*)d_in[16];
    const float* outW   = (const float*)d_in[17];
    const float* outb   = (const float*)d_in[18];

    int B  = in_sizes[0] / (TSEQ * NINP);
    int TL = out_size / B;                       // 180
    int grid = (B + ROWS - 1) / ROWS;            // 128
    size_t smem = SMEM_FLOATS * sizeof(float);   // ~174 KB

    cudaFuncSetAttribute(gru_kernel,
                         cudaFuncAttributeMaxDynamicSharedMemorySize,
                         (int)smem);

    gru_kernel<<<grid, NT, smem>>>(
        x, eWih0, eWhh0, ebih0, ebhh0, eWih1, eWhh1, ebih1, ebhh1,
        dWih0, dWhh0, dbih0, dbhh0, dWih1, dWhh1, dbih1, dbhh1,
        outW, outb, (float*)d_out, B, TL);
}

// round 3
// speedup vs baseline: 1.0798x; 1.0798x over previous
#include <cuda_runtime.h>

// ---------------------------------------------------------------------------
// GRU encoder-decoder, persistent per-CTA recurrence, f32x2-packed compute.
// One CTA = 32 batch rows, 256 threads; thread tile = 4 rows x 2 units with
// the 2 units packed into f32x2 lanes (weights load as natural LDS.64 pairs).
// Double-buffered hidden state -> 2 syncs/enc step, 3 syncs/dec step.
// ---------------------------------------------------------------------------

typedef unsigned long long u64;

#define Hh     64
#define G3     192
#define ROWS   32
#define NT     256
#define TSEQ   256
#define NINP   6

// SMEM float offsets
#define OFF_WX0   0        // [8][192]
#define OFF_WH0   1536     // [64][192]
#define OFF_WX1   13824    // [64][192]
#define OFF_WH1   26112    // [64][192]
#define OFF_HS0   38400    // [2][64][32]
#define OFF_HS1   42496    // [2][64][32]
#define OFF_XS    46592    // [2][8][32]
#define OFF_OW    47104    // [64]
#define OFF_OB    47168    // [1]
#define SMEM_FLOATS 47172  // 188,688 bytes

__device__ __forceinline__ u64 pk2(float lo, float hi) {
    u64 r; asm("mov.b64 %0, {%1,%2};" : "=l"(r) : "f"(lo), "f"(hi)); return r;
}
__device__ __forceinline__ u64 dup2(float v) { return pk2(v, v); }
__device__ __forceinline__ float2 up2(u64 v) {
    float2 r; asm("mov.b64 {%0,%1}, %2;" : "=f"(r.x), "=f"(r.y) : "l"(v)); return r;
}
#define FFMA2(acc, a, b) \
    asm("fma.rn.f32x2 %0, %1, %2, %0;" : "+l"(acc) : "l"(a), "l"(b))

__device__ __forceinline__ float sigf(float x) {
    return 1.0f / (1.0f + __expf(-x));
}
__device__ __forceinline__ float tanhfast(float x) {
    float e = __expf(-2.0f * fabsf(x));
    float t = (1.0f - e) / (1.0f + e);
    return copysignf(t, x);
}

// Transpose-load W[192][K] (row-major) -> dst[k*192 + g]
__device__ __forceinline__ void load_wT(float* dst, const float* __restrict__ src,
                                        int K, int tid) {
    for (int idx = tid; idx < G3 * K; idx += NT) {
        int g = idx / K;
        int k = idx - g * K;
        dst[k * G3 + g] = src[idx];
    }
}

// One GRU cell for this thread's [2 units (packed) x 4 rows] tile.
// xsrc/hsrc k-major [k][ROWS]; Wx/Wh k-major [k][192], gates r|z|n.
// Writes new h into hdst (double buffer). Bias pairs pre-packed in regs.
template<int KIN>
__device__ __forceinline__ void gru_tile2(
    const float* __restrict__ Wx, const float* __restrict__ Wh,
    const float* __restrict__ xsrc, const float* __restrict__ hsrc,
    float* __restrict__ hdst,
    u64 br2, u64 bz2, u64 bi2, u64 bh2,
    int j0, int r0)
{
    u64 ar[4], az[4], ai[4], ah[4];
#pragma unroll
    for (int rr = 0; rr < 4; rr++) { ar[rr] = br2; az[rr] = bz2; ai[rr] = bi2; ah[rr] = bh2; }

    const float* wxp = Wx + j0;
#pragma unroll
    for (int k = 0; k < KIN; k++) {
        float4 xv = *(const float4*)(xsrc + k * ROWS + r0);
        u64 wr = *(const u64*)(wxp + k * G3);
        u64 wz = *(const u64*)(wxp + k * G3 + 64);
        u64 wn = *(const u64*)(wxp + k * G3 + 128);
        u64 x0 = dup2(xv.x), x1 = dup2(xv.y), x2 = dup2(xv.z), x3 = dup2(xv.w);
        FFMA2(ar[0], wr, x0); FFMA2(ar[1], wr, x1); FFMA2(ar[2], wr, x2); FFMA2(ar[3], wr, x3);
        FFMA2(az[0], wz, x0); FFMA2(az[1], wz, x1); FFMA2(az[2], wz, x2); FFMA2(az[3], wz, x3);
        FFMA2(ai[0], wn, x0); FFMA2(ai[1], wn, x1); FFMA2(ai[2], wn, x2); FFMA2(ai[3], wn, x3);
    }

    const float* whp = Wh + j0;
#pragma unroll 8
    for (int k = 0; k < Hh; k++) {
        float4 hv = *(const float4*)(hsrc + k * ROWS + r0);
        u64 wr = *(const u64*)(whp + k * G3);
        u64 wz = *(const u64*)(whp + k * G3 + 64);
        u64 wn = *(const u64*)(whp + k * G3 + 128);
        u64 h0 = dup2(hv.x), h1 = dup2(hv.y), h2 = dup2(hv.z), h3 = dup2(hv.w);
        FFMA2(ar[0], wr, h0); FFMA2(ar[1], wr, h1); FFMA2(ar[2], wr, h2); FFMA2(ar[3], wr, h3);
        FFMA2(az[0], wz, h0); FFMA2(az[1], wz, h1); FFMA2(az[2], wz, h2); FFMA2(az[3], wz, h3);
        FFMA2(ah[0], wn, h0); FFMA2(ah[1], wn, h1); FFMA2(ah[2], wn, h2); FFMA2(ah[3], wn, h3);
    }

    // epilogue: r,z sigmoid; n = tanh(in + r*hn); h' = n + z*(h_old - n)
    float4 hold0 = *(const float4*)(hsrc + j0 * ROWS + r0);
    float4 hold1 = *(const float4*)(hsrc + (j0 + 1) * ROWS + r0);
    float ho0[4] = {hold0.x, hold0.y, hold0.z, hold0.w};
    float ho1[4] = {hold1.x, hold1.y, hold1.z, hold1.w};
    float o0[4], o1[4];
#pragma unroll
    for (int rr = 0; rr < 4; rr++) {
        float2 arv = up2(ar[rr]), azv = up2(az[rr]);
        float2 aiv = up2(ai[rr]), ahv = up2(ah[rr]);
        {   // unit 0
            float r = sigf(arv.x), z = sigf(azv.x);
            float n = tanhfast(fmaf(r, ahv.x, aiv.x));
            o0[rr] = fmaf(z, ho0[rr] - n, n);
        }
        {   // unit 1
            float r = sigf(arv.y), z = sigf(azv.y);
            float n = tanhfast(fmaf(r, ahv.y, aiv.y));
            o1[rr] = fmaf(z, ho1[rr] - n, n);
        }
    }
    *(float4*)(hdst + j0 * ROWS + r0)       = make_float4(o0[0], o0[1], o0[2], o0[3]);
    *(float4*)(hdst + (j0 + 1) * ROWS + r0) = make_float4(o1[0], o1[1], o1[2], o1[3]);
}

extern __shared__ float sm[];

__global__ __launch_bounds__(NT, 1)
void gru_kernel(
    const float* __restrict__ x,
    const float* __restrict__ eWih0, const float* __restrict__ eWhh0,
    const float* __restrict__ ebih0, const float* __restrict__ ebhh0,
    const float* __restrict__ eWih1, const float* __restrict__ eWhh1,
    const float* __restrict__ ebih1, const float* __restrict__ ebhh1,
    const float* __restrict__ dWih0, const float* __restrict__ dWhh0,
    const float* __restrict__ dbih0, const float* __restrict__ dbhh0,
    const float* __restrict__ dWih1, const float* __restrict__ dWhh1,
    const float* __restrict__ dbih1, const float* __restrict__ dbhh1,
    const float* __restrict__ outW, const float* __restrict__ outb,
    float* __restrict__ out, int Bn, int TL)
{
    const int tid = threadIdx.x;
    const int b0  = blockIdx.x * ROWS;

    float* Wx0 = sm + OFF_WX0;
    float* Wh0 = sm + OFF_WH0;
    float* Wx1 = sm + OFF_WX1;
    float* Wh1 = sm + OFF_WH1;
    float* hs0 = sm + OFF_HS0;
    float* hs1 = sm + OFF_HS1;
    float* xs  = sm + OFF_XS;
    float* sOW = sm + OFF_OW;
    float* sOB = sm + OFF_OB;

    const int rt = tid & 7;
    const int ut = tid >> 3;
    const int r0 = rt * 4;
    const int j0 = ut * 2;

    // ---- stage encoder weights ----
    load_wT(Wx0, eWih0, NINP, tid);
    load_wT(Wh0, eWhh0, Hh, tid);
    load_wT(Wx1, eWih1, Hh, tid);
    load_wT(Wh1, eWhh1, Hh, tid);
    for (int i = tid; i < Hh * ROWS; i += NT) {
        hs0[i] = 0.0f; hs0[2048 + i] = 0.0f;
        hs1[i] = 0.0f; hs1[2048 + i] = 0.0f;
    }

    // ---- encoder bias pairs in registers ----
    u64 b0r, b0z, b0i, b0h, b1r, b1z, b1i, b1h;
    {
        float2 a, b;
        a = *(const float2*)(ebih0 + j0);        b = *(const float2*)(ebhh0 + j0);
        b0r = pk2(a.x + b.x, a.y + b.y);
        a = *(const float2*)(ebih0 + 64 + j0);   b = *(const float2*)(ebhh0 + 64 + j0);
        b0z = pk2(a.x + b.x, a.y + b.y);
        a = *(const float2*)(ebih0 + 128 + j0);  b0i = pk2(a.x, a.y);
        b = *(const float2*)(ebhh0 + 128 + j0);  b0h = pk2(b.x, b.y);
        a = *(const float2*)(ebih1 + j0);        b = *(const float2*)(ebhh1 + j0);
        b1r = pk2(a.x + b.x, a.y + b.y);
        a = *(const float2*)(ebih1 + 64 + j0);   b = *(const float2*)(ebhh1 + 64 + j0);
        b1z = pk2(a.x + b.x, a.y + b.y);
        a = *(const float2*)(ebih1 + 128 + j0);  b1i = pk2(a.x, a.y);
        b = *(const float2*)(ebhh1 + 128 + j0);  b1h = pk2(b.x, b.y);
    }

    // prestage x for t=0 into buffer 0
    const int xi = tid >> 5, xr = tid & 31;
    if (tid < NINP * ROWS) {
        float v = (b0 + xr < Bn)
            ? x[(size_t)(b0 + xr) * (TSEQ * NINP) + xi] : 0.0f;
        xs[xi * ROWS + xr] = v;
    }
    __syncthreads();

    // ---- encoder: 256 steps ----
    int cur = 0;
    for (int t = 0; t < TSEQ; t++) {
        // prefetch x for t+1 (hidden behind compute)
        float xreg = 0.0f;
        if (tid < NINP * ROWS && t + 1 < TSEQ && b0 + xr < Bn)
            xreg = x[(size_t)(b0 + xr) * (TSEQ * NINP) + (size_t)(t + 1) * NINP + xi];
        int nxt = cur ^ 1;
        gru_tile2<NINP>(Wx0, Wh0, xs + cur * 256, hs0 + cur * 2048,
                        hs0 + nxt * 2048, b0r, b0z, b0i, b0h, j0, r0);
        if (tid < NINP * ROWS) xs[nxt * 256 + xi * ROWS + xr] = xreg;
        __syncthreads();
        gru_tile2<Hh>(Wx1, Wh1, hs0 + nxt * 2048, hs1 + cur * 2048,
                      hs1 + nxt * 2048, b1r, b1z, b1i, b1h, j0, r0);
        cur = nxt;
        __syncthreads();
    }

    // ---- swap in decoder weights ----
    load_wT(Wx0, dWih0, 1, tid);
    load_wT(Wh0, dWhh0, Hh, tid);
    load_wT(Wx1, dWih1, Hh, tid);
    load_wT(Wh1, dWhh1, Hh, tid);
    if (tid < Hh) sOW[tid] = outW[tid];
    if (tid == 0) sOB[0] = outb[0];
    if (tid < ROWS) xs[tid] = 0.0f;      // prev cv = 0, stored in xs row 0
    {
        float2 a, b;
        a = *(const float2*)(dbih0 + j0);        b = *(const float2*)(dbhh0 + j0);
        b0r = pk2(a.x + b.x, a.y + b.y);
        a = *(const float2*)(dbih0 + 64 + j0);   b = *(const float2*)(dbhh0 + 64 + j0);
        b0z = pk2(a.x + b.x, a.y + b.y);
        a = *(const float2*)(dbih0 + 128 + j0);  b0i = pk2(a.x, a.y);
        b = *(const float2*)(dbhh0 + 128 + j0);  b0h = pk2(b.x, b.y);
        a = *(const float2*)(dbih1 + j0);        b = *(const float2*)(dbhh1 + j0);
        b1r = pk2(a.x + b.x, a.y + b.y);
        a = *(const float2*)(dbih1 + 64 + j0);   b = *(const float2*)(dbhh1 + 64 + j0);
        b1z = pk2(a.x + b.x, a.y + b.y);
        a = *(const float2*)(dbih1 + 128 + j0);  b1i = pk2(a.x, a.y);
        b = *(const float2*)(dbhh1 + 128 + j0);  b1h = pk2(b.x, b.y);
    }
    __syncthreads();

    // ---- decoder: TL autoregressive steps ----
    for (int s = 0; s < TL; s++) {
        int nxt = cur ^ 1;
        gru_tile2<1>(Wx0, Wh0, xs, hs0 + cur * 2048,
                     hs0 + nxt * 2048, b0r, b0z, b0i, b0h, j0, r0);
        __syncthreads();
        gru_tile2<Hh>(Wx1, Wh1, hs0 + nxt * 2048, hs1 + cur * 2048,
                      hs1 + nxt * 2048, b1r, b1z, b1i, b1h, j0, r0);
        __syncthreads();
        if (tid < ROWS) {
            float acc = sOB[0];
            const float* hp = hs1 + nxt * 2048 + tid;
            #pragma unroll 8
            for (int j = 0; j < Hh; j++)
                acc = fmaf(sOW[j], hp[j * ROWS], acc);
            if (b0 + tid < Bn)
                out[(size_t)(b0 + tid) * TL + s] = acc;
            xs[tid] = acc;
        }
        cur = nxt;
        __syncthreads();
    }
}

extern "C" void kernel_launch(void* const* d_in, const int* in_sizes, int n_in,
                              void* d_out, int out_size) {
    const float* x      = (const float*)d_in[0];
    const float* eWih0  = (const float*)d_in[1];
    const float* eWhh0  = (const float*)d_in[2];
    const float* ebih0  = (const float*)d_in[3];
    const float* ebhh0  = (const float*)d_in[4];
    const float* eWih1  = (const float*)d_in[5];
    const float* eWhh1  = (const float*)d_in[6];
    const float* ebih1  = (const float*)d_in[7];
    const float* ebhh1  = (const float*)d_in[8];
    const float* dWih0  = (const float*)d_in[9];
    const float* dWhh0  = (const float*)d_in[10];
    const float* dbih0  = (const float*)d_in[11];
    const float* dbhh0  = (const float*)d_in[12];
    const float* dWih1  = (const float*)d_in[13];
    const float* dWhh1  = (const float*)d_in[14];
    const float* dbih1  = (const float*)d_in[15];
    const float* dbhh1  = (const float*)d_in[16];
    const float* outW   = (const float*)d_in[17];
    const float* outb   = (const float*)d_in[18];

    int B  = in_sizes[0] / (TSEQ * NINP);
    int TL = out_size / B;                       // 180
    int grid = (B + ROWS - 1) / ROWS;            // 128
    size_t smem = SMEM_FLOATS * sizeof(float);   // ~188 KB

    cudaFuncSetAttribute(gru_kernel,
                         cudaFuncAttributeMaxDynamicSharedMemorySize,
                         (int)smem);

    gru_kernel<<<grid, NT, smem>>>(
        x, eWih0, eWhh0, ebih0, ebhh0, eWih1, eWhh1, ebih1, ebhh1,
        dWih0, dWhh0, dbih0, dbhh0, dWih1, dWhh1, dbih1, dbhh1,
        outW, outb, (float*)d_out, B, TL);
}